// round 16
// baseline (speedup 1.0000x reference)
#include <cuda_runtime.h>
#include <cuda_bf16.h>
#include <cstdint>

// LengthRegulator, single launch, front-of-grid slice producers:
//   x (32,512,384) f32, duration (32,512) int64/int32 (runtime-detected), max_len=4096
//   out = (32,4096,384) f32 + mel_len tail (layout inferred from out_size).
//
// Grid = 4096 blocks of (96,4); block n expands output rows [32n, 32n+32).
// Blocks 0..255 are ALSO producers (all resident in wave 1): block p scans
// batch (p/8)'s 512 durations and inverse-scatters g_idx slice (p%8) of 512
// positions (~1-1.5us, 256-way parallel). Single global counter releases all
// consumers (proven safe at 8192 pollers in R10; here only 4096).

#define B_    32
#define T_    512
#define C_    384
#define ML_   4096
#define C4_   (C_ / 4)            // 96 float4 per row
#define RPB   32                  // rows per expand block
#define NTHR  (C4_ * 4)           // 384 threads
#define SPB   8                   // producer slices per batch
#define SLC   (ML_ / SPB)         // 512 positions per slice
#define NPROD (B_ * SPB)          // 256 producer blocks
#define GRID  ((B_ * ML_) / RPB)  // 4096 blocks

__device__ int g_idx[B_ * ML_];   // input-row index per output row; -1 = masked
__device__ int g_ready;           // producer completion counter (self-resetting)
__device__ unsigned int g_done;   // block completion counter (self-resetting)

__global__ void __launch_bounds__(NTHR) lr_fused_kernel(const float4* __restrict__ x,
                                                        const void* __restrict__ dur_raw,
                                                        float* __restrict__ out,
                                                        int mel_mode) {
    const int c4  = threadIdx.x;              // 0..95
    const int ty  = threadIdx.y;              // 0..3
    const int tid = ty * C4_ + c4;            // 0..383

    // ================= PRODUCER: blocks 0..255, one (batch, slice) each ==========
    if (blockIdx.x < NPROD) {
        __shared__ int s_csum[T_];
        __shared__ int s_wsum[16];
        const int pb   = blockIdx.x >> 3;           // producer's batch
        const int ps   = blockIdx.x & (SPB - 1);    // slice within batch
        const int lane = tid & 31;
        const int wid  = tid >> 5;                  // 0..11

        // int64 vs int32: odd int32 words of first 512 elements all zero => int64
        int pred = 0;
        for (int i = tid; i < T_; i += NTHR)
            pred |= ((const int*)dur_raw)[2 * i + 1];
        const int is32 = __syncthreads_or(pred != 0);

        for (int i = tid; i < T_; i += NTHR) {
            long long dv;
            if (is32) dv = (long long)((const int*)dur_raw)[(size_t)pb * T_ + i];
            else      dv = ((const long long*)dur_raw)[(size_t)pb * T_ + i];
            s_csum[i] = dv > 0 ? (int)dv : 0;
        }
        __syncthreads();

        // inclusive scan: 16 chunks of 32, warps 0..11 sweep chunks
        for (int chunk = wid; chunk < 16; chunk += 12) {
            int v = s_csum[chunk * 32 + lane];
            #pragma unroll
            for (int off = 1; off < 32; off <<= 1) {
                int n = __shfl_up_sync(0xffffffffu, v, off);
                if (lane >= off) v += n;
            }
            s_csum[chunk * 32 + lane] = v;
            if (lane == 31) s_wsum[chunk] = v;
        }
        __syncthreads();
        if (wid == 0) {
            int wv = (lane < 16) ? s_wsum[lane] : 0;
            #pragma unroll
            for (int off = 1; off < 16; off <<= 1) {
                int n = __shfl_up_sync(0xffffffffu, wv, off);
                if (lane >= off) wv += n;
            }
            if (lane < 16) s_wsum[lane] = wv;
        }
        __syncthreads();
        for (int i = tid; i < T_; i += NTHR)
            if (i >= 32) s_csum[i] += s_wsum[(i >> 5) - 1];
        __syncthreads();

        const int mel = s_csum[T_ - 1];

        // mel tail: slice-0 producer of each batch
        if (ps == 0 && tid == 0) {
            const size_t total = (size_t)B_ * ML_ * C_;
            if (mel_mode == 1)      out[total + pb] = (float)mel;
            else if (mel_mode == 2) ((long long*)(out + total))[pb] = (long long)mel;
        }

        // inverse scatter restricted to slice [p0, p1)
        const int p0 = ps * SLC;
        const int p1 = p0 + SLC;
        int* gb = g_idx + pb * ML_;
        for (int i = tid; i < T_; i += NTHR) {
            int start = (i == 0) ? 0 : s_csum[i - 1];
            int end   = s_csum[i];
            if (start < p0) start = p0;
            if (end   > p1) end   = p1;
            for (int p = start; p < end; ++p) gb[p] = i;
        }
        int mstart = mel > p0 ? mel : p0;      // masked tail within slice
        for (int p = mstart + tid; p < p1; p += NTHR) gb[p] = -1;

        __threadfence();                       // publish g_idx before signaling
        __syncthreads();
        if (tid == 0) atomicAdd(&g_ready, 1);
    }

    // ================= WAIT: until all 256 producers signaled =================
    if (tid == 0) {
        volatile int* r = &g_ready;
        while (*r < NPROD) __nanosleep(64);
        __threadfence();                       // acquire before consuming g_idx
    }
    __syncthreads();

    // ================= EXPAND: proven HBM-write-floor body (MLP-8) ============
    const int rowBase = blockIdx.x * RPB + ty;           // rows: rowBase + 4*k
    const int b       = (blockIdx.x * RPB) >> 12;        // batch (RPB | ML_)

    int idx[8];
    #pragma unroll
    for (int k = 0; k < 8; ++k)
        idx[k] = g_idx[rowBase + 4 * k];                 // warp-uniform

    const float4* xb = x + (size_t)b * T_ * C4_;
    float4* out4 = (float4*)out;

    #pragma unroll
    for (int g = 0; g < 2; ++g) {
        float4 v[4];
        #pragma unroll
        for (int k = 0; k < 4; ++k) {
            const int kk = g * 4 + k;
            if (idx[kk] >= 0) v[k] = __ldg(&xb[(size_t)idx[kk] * C4_ + c4]);
            else              v[k] = make_float4(0.f, 0.f, 0.f, 0.f);
        }
        #pragma unroll
        for (int k = 0; k < 4; ++k)
            out4[(size_t)(rowBase + 4 * (g * 4 + k)) * C4_ + c4] = v[k];
    }

    // ================= RESET flags (last block) for deterministic replay ======
    __syncthreads();
    if (tid == 0) {
        if (atomicAdd(&g_done, 1u) == (unsigned)(GRID - 1)) {
            g_done  = 0u;
            g_ready = 0;
        }
    }
}

// ---------------------------------------------------------------------------
extern "C" void kernel_launch(void* const* d_in, const int* in_sizes, int n_in,
                              void* d_out, int out_size) {
    const float* x   = (const float*)d_in[0];
    const void*  dur = d_in[1];
    float* out = (float*)d_out;

    const long long total = (long long)B_ * ML_ * C_;
    const long long extra = (long long)out_size - total;
    int mel_mode = 0;
    if (extra == B_)          mel_mode = 1;   // float32 tail
    else if (extra == 2 * B_) mel_mode = 2;   // raw int64 tail

    dim3 blk(C4_, 4);
    lr_fused_kernel<<<GRID, blk>>>((const float4*)x, dur, out, mel_mode);
}

// round 17
// speedup vs baseline: 1.1191x; 1.1191x over previous
#include <cuda_runtime.h>
#include <cuda_bf16.h>
#include <cstdint>

// LengthRegulator, two-kernel with PDL (programmatic dependent launch):
//   x (32,512,384) f32, duration (32,512) int64/int32 (runtime-detected), max_len=4096
//   out = (32,4096,384) f32 + mel_len tail (layout inferred from out_size).
//
// K1 (256 blocks, 8/batch): per-block shuffle scan + inverse-scatter of a
//     512-position g_idx slice, then griddepcontrol.launch_dependents.
// K2 (4096 blocks, PDL secondary): launches while K1 runs; prefetches its 6KB
//     share of x into L2 (24MB total = whole x) BEFORE griddepcontrol.wait,
//     then runs the proven MLP-8 write-floor expand. K1 + launch gap + x-read
//     phase all overlap.

#define B_   32
#define T_   512
#define C_   384
#define ML_  4096
#define C4_  (C_ / 4)            // 96 float4 per row
#define RPB  32                  // rows per expand block
#define NTHR (C4_ * 4)           // 384 threads
#define SPB  8                   // scan blocks per batch
#define SLC  (ML_ / SPB)         // 512 output positions per scan block
#define EBPB (ML_ / RPB)         // 128 expand blocks per batch

__device__ int g_idx[B_ * ML_];  // input-row index per output row; -1 = masked

// ---------------------------------------------------------------------------
// Kernel 1: grid = 256, block = 512. Scan batch durations, scatter g_idx slice,
// then allow dependent launch.
// ---------------------------------------------------------------------------
__global__ void __launch_bounds__(T_) lr_scan_kernel(const void* __restrict__ dur_raw,
                                                     float* __restrict__ out,
                                                     int mel_mode) {
    __shared__ int s_csum[T_];
    __shared__ int s_wsum[16];

    const int t    = threadIdx.x;
    const int b    = blockIdx.x >> 3;           // batch
    const int s    = blockIdx.x & (SPB - 1);    // slice within batch
    const int lane = t & 31;
    const int wid  = t >> 5;

    // int64 vs int32: odd int32 words of first 512 elements all zero => int64
    int pred = ((const int*)dur_raw)[2 * t + 1];
    const int is32 = __syncthreads_or(pred != 0);

    long long dv;
    if (is32) dv = (long long)((const int*)dur_raw)[(size_t)b * T_ + t];
    else      dv = ((const long long*)dur_raw)[(size_t)b * T_ + t];
    int v = dv > 0 ? (int)dv : 0;

    // warp inclusive scan
    #pragma unroll
    for (int off = 1; off < 32; off <<= 1) {
        int n = __shfl_up_sync(0xffffffffu, v, off);
        if (lane >= off) v += n;
    }
    if (lane == 31) s_wsum[wid] = v;
    __syncthreads();
    if (wid == 0) {
        int wv = (lane < 16) ? s_wsum[lane] : 0;
        #pragma unroll
        for (int off = 1; off < 16; off <<= 1) {
            int n = __shfl_up_sync(0xffffffffu, wv, off);
            if (lane >= off) wv += n;
        }
        if (lane < 16) s_wsum[lane] = wv;
    }
    __syncthreads();
    if (wid > 0) v += s_wsum[wid - 1];
    s_csum[t] = v;
    __syncthreads();

    const int mel = s_csum[T_ - 1];

    // mel tail (one block per batch)
    if (s == 0 && t == 0) {
        const size_t total = (size_t)B_ * ML_ * C_;
        if (mel_mode == 1)      out[total + b] = (float)mel;
        else if (mel_mode == 2) ((long long*)(out + total))[b] = (long long)mel;
    }

    // inverse scatter restricted to this block's slice [p0, p1)
    const int p0 = s * SLC;
    const int p1 = p0 + SLC;
    int* gb = g_idx + b * ML_;

    {   // thread t owns input row t: fill [csum[t-1], csum[t]) ∩ [p0, p1)
        int start = (t == 0) ? 0 : s_csum[t - 1];
        int end   = s_csum[t];
        if (start < p0) start = p0;
        if (end   > p1) end   = p1;
        for (int p = start; p < end; ++p) gb[p] = t;
    }
    {   // masked tail within slice: [max(mel,p0), p1)
        int mstart = mel > p0 ? mel : p0;
        for (int p = mstart + t; p < p1; p += T_) gb[p] = -1;
    }

    __threadfence();     // make g_idx globally visible before releasing dependents
    asm volatile("griddepcontrol.launch_dependents;" ::: "memory");
}

// ---------------------------------------------------------------------------
// Kernel 2 (PDL secondary): prefetch x share -> wait -> MLP-8 expand.
// grid = 4096, block (96,4).
// ---------------------------------------------------------------------------
__global__ void __launch_bounds__(NTHR) lr_expand_kernel(const float4* __restrict__ x,
                                                         float4* __restrict__ out) {
    const int c4  = threadIdx.x;                       // 0..95
    const int ty  = threadIdx.y;                       // 0..3
    const int tid = ty * C4_ + c4;                     // 0..383

    const int b   = blockIdx.x / EBPB;                 // batch
    const int bib = blockIdx.x - b * EBPB;             // block within batch
    const float4* xb = x + (size_t)b * T_ * C4_;

    // Prefetch this block's 6KB share of the batch's x slice (covers all of x
    // across the grid) — overlaps K1 execution + our own scheduling latency.
    if (tid < 48) {
        const float4* pf = xb + (size_t)bib * 384 + tid * 8;
        asm volatile("prefetch.global.L2 [%0];" :: "l"(pf));
    }

    // Wait for K1 (g_idx published).
    asm volatile("griddepcontrol.wait;" ::: "memory");

    const int rowBase = blockIdx.x * RPB + ty;         // rows: rowBase + 4*k, k=0..7

    int idx[8];
    #pragma unroll
    for (int k = 0; k < 8; ++k)
        idx[k] = g_idx[rowBase + 4 * k];               // warp-uniform

    #pragma unroll
    for (int g = 0; g < 2; ++g) {
        float4 v[4];
        #pragma unroll
        for (int k = 0; k < 4; ++k) {
            const int kk = g * 4 + k;
            if (idx[kk] >= 0) v[k] = __ldg(&xb[(size_t)idx[kk] * C4_ + c4]);
            else              v[k] = make_float4(0.f, 0.f, 0.f, 0.f);
        }
        #pragma unroll
        for (int k = 0; k < 4; ++k)
            out[(size_t)(rowBase + 4 * (g * 4 + k)) * C4_ + c4] = v[k];
    }
}

// ---------------------------------------------------------------------------
extern "C" void kernel_launch(void* const* d_in, const int* in_sizes, int n_in,
                              void* d_out, int out_size) {
    const float* x   = (const float*)d_in[0];
    const void*  dur = d_in[1];
    float* out = (float*)d_out;

    const long long total = (long long)B_ * ML_ * C_;
    const long long extra = (long long)out_size - total;
    int mel_mode = 0;
    if (extra == B_)          mel_mode = 1;   // float32 tail
    else if (extra == 2 * B_) mel_mode = 2;   // raw int64 tail

    lr_scan_kernel<<<B_ * SPB, T_>>>(dur, out, mel_mode);

    // K2 with programmatic dependent launch: boots while K1 still runs.
    cudaLaunchConfig_t cfg = {};
    cfg.gridDim  = dim3((B_ * ML_) / RPB, 1, 1);
    cfg.blockDim = dim3(C4_, 4, 1);
    cudaLaunchAttribute attrs[1];
    attrs[0].id = cudaLaunchAttributeProgrammaticStreamSerialization;
    attrs[0].val.programmaticStreamSerializationAllowed = 1;
    cfg.attrs    = attrs;
    cfg.numAttrs = 1;
    cudaLaunchKernelEx(&cfg, lr_expand_kernel, (const float4*)x, (float4*)out);
}